// round 5
// baseline (speedup 1.0000x reference)
#include <cuda_runtime.h>
#include <cstdint>
#include <cstddef>

// ---------------- problem constants ----------------
#define DIMD   2048
#define MTOT   16384            // 4*4096 tokens
#define N1     6144             // 3*DIMD
#define KD     2048
#define SEQ    4096

// ---------------- scratch ----------------
__device__ float g_xn[(size_t)MTOT * KD];
__device__ float g_h [(size_t)MTOT * N1];
__device__ float g_o [(size_t)MTOT * KD];
__device__ float g_We[(size_t)N1  * KD];
__device__ float g_Wp[(size_t)KD  * KD];

// ---------------- helpers ----------------
__device__ __forceinline__ float to_tf32(float x) {
    float r; asm("cvt.rna.tf32.f32 %0, %1;" : "=f"(r) : "f"(x)); return r;
}
__device__ __forceinline__ void cpasync16(void* smem, const void* gmem) {
    uint32_t s = (uint32_t)__cvta_generic_to_shared(smem);
    asm volatile("cp.async.cg.shared.global [%0], [%1], 16;" :: "r"(s), "l"(gmem));
}
#define CP_COMMIT() asm volatile("cp.async.commit_group;")
#define CP_WAIT1()  asm volatile("cp.async.wait_group 1;")

__device__ __forceinline__ void mma_tf32(float c[4], const uint32_t a[4], const uint32_t b[2]) {
    asm volatile(
        "mma.sync.aligned.m16n8k8.row.col.f32.tf32.tf32.f32 "
        "{%0,%1,%2,%3}, {%4,%5,%6,%7}, {%8,%9}, {%0,%1,%2,%3};"
        : "+f"(c[0]), "+f"(c[1]), "+f"(c[2]), "+f"(c[3])
        : "r"(a[0]), "r"(a[1]), "r"(a[2]), "r"(a[3]),
          "r"(b[0]), "r"(b[1]));
}

// ---------------- tf32 GEMM v5: C[M,N] = A[M,K] * B[N,K]^T ----------------
// CTA 128x256, 512 threads = 16 warps (2M x 8N), warp tile 64x32.
// 4 warps/SMSP hide LDS latency; single-buffered fragments (reg cap 128).
// BK=32, 3-stage cp.async pipeline.
constexpr int BM = 128, BN = 256, BK = 32, NSTG = 3;
constexpr int NTHREADS = 512;
constexpr int LDS_STRIDE = BK + 4;                   // 36 floats
constexpr int A_FLOATS = BM * LDS_STRIDE;            // 4608
constexpr int B_FLOATS = BN * LDS_STRIDE;            // 9216
constexpr int STG_FLOATS = A_FLOATS + B_FLOATS;      // 13824
constexpr int SMEM_SZ = NSTG * STG_FLOATS * 4;       // 165888 B

template<int N, bool FUSE>
__global__ void __launch_bounds__(NTHREADS, 1) gemm_k(const float* __restrict__ A,
                                                      const float* __restrict__ B,
                                                      float* __restrict__ C,
                                                      const float* __restrict__ xres,
                                                      const float* __restrict__ cs) {
    constexpr int K = KD;
    constexpr int KT = K / BK;    // 64
    extern __shared__ float smem[];

    const int bm = blockIdx.y * BM;
    const int bn = blockIdx.x * BN;
    const int tid  = threadIdx.x;
    const int warp = tid >> 5, lane = tid & 31;
    const int wm = (warp & 1) * 64;          // 2 warps along M
    const int wn = (warp >> 1) * 32;         // 8 warps along N
    const int gid = lane >> 2, tig = lane & 3;

    float acc[4][4][4];
    #pragma unroll
    for (int mi = 0; mi < 4; mi++)
        #pragma unroll
        for (int ni = 0; ni < 4; ni++)
            #pragma unroll
            for (int r = 0; r < 4; r++) acc[mi][ni][r] = 0.f;

    const float* Abase = A + (size_t)bm * K;
    const float* Bbase = B + (size_t)bn * K;

    auto load_stage = [&](int kt) {
        float* sa = smem + (kt % NSTG) * STG_FLOATS;
        float* sb = sa + A_FLOATS;
        const float* Ag = Abase + kt * BK;
        const float* Bg = Bbase + kt * BK;
        // A: 128 rows x 8 chunks(16B) = 1024, 2 per thread
        #pragma unroll
        for (int i = 0; i < 2; i++) {
            int c = tid + i * NTHREADS;
            int row = c >> 3, ck = c & 7;
            cpasync16(sa + row * LDS_STRIDE + ck * 4, Ag + (size_t)row * K + ck * 4);
        }
        // B: 256 rows x 8 chunks = 2048, 4 per thread
        #pragma unroll
        for (int i = 0; i < 4; i++) {
            int c = tid + i * NTHREADS;
            int row = c >> 3, ck = c & 7;
            cpasync16(sb + row * LDS_STRIDE + ck * 4, Bg + (size_t)row * K + ck * 4);
        }
    };

    // prologue: 2 stages in flight
    load_stage(0); CP_COMMIT();
    load_stage(1); CP_COMMIT();
    CP_WAIT1();
    __syncthreads();

    #pragma unroll 1
    for (int kt = 0; kt < KT; kt++) {
        const float* sa = smem + (kt % NSTG) * STG_FLOATS;
        const float* sb = sa + A_FLOATS;

        if (kt + 2 < KT) load_stage(kt + 2);
        CP_COMMIT();

        #pragma unroll
        for (int ks = 0; ks < 4; ks++) {
            const int k0 = ks * 8;
            uint32_t fa[4][4], fb[4][2];
            #pragma unroll
            for (int mi = 0; mi < 4; mi++) {
                const float* p = sa + (wm + mi * 16 + gid) * LDS_STRIDE + k0;
                fa[mi][0] = __float_as_uint(p[tig]);
                fa[mi][1] = __float_as_uint(p[8 * LDS_STRIDE + tig]);
                fa[mi][2] = __float_as_uint(p[tig + 4]);
                fa[mi][3] = __float_as_uint(p[8 * LDS_STRIDE + tig + 4]);
            }
            #pragma unroll
            for (int ni = 0; ni < 4; ni++) {
                const float* p = sb + (wn + ni * 8 + gid) * LDS_STRIDE + k0;
                fb[ni][0] = __float_as_uint(p[tig]);
                fb[ni][1] = __float_as_uint(p[tig + 4]);
            }
            #pragma unroll
            for (int mi = 0; mi < 4; mi++)
                #pragma unroll
                for (int ni = 0; ni < 4; ni++)
                    mma_tf32(acc[mi][ni], fa[mi], fb[ni]);
        }

        if (kt + 1 < KT) {
            CP_WAIT1();
            __syncthreads();
        }
    }

    // epilogue
    #pragma unroll
    for (int mi = 0; mi < 4; mi++) {
        #pragma unroll
        for (int ni = 0; ni < 4; ni++) {
            int r0 = bm + wm + mi * 16 + gid;
            int c0 = bn + wn + ni * 8 + tig * 2;
            #pragma unroll
            for (int h = 0; h < 2; h++) {
                int r = r0 + h * 8;
                size_t off = (size_t)r * N + c0;
                float v0 = acc[mi][ni][2 * h + 0];
                float v1 = acc[mi][ni][2 * h + 1];
                if (FUSE) {
                    v0 = xres[off]     + cs[c0]     * v0;
                    v1 = xres[off + 1] + cs[c0 + 1] * v1;
                }
                float2 st; st.x = v0; st.y = v1;
                *(float2*)(C + off) = st;
            }
        }
    }
}

// ---------------- prep: round weights to tf32 (RNA) ----------------
__global__ void round_We_k(const float* __restrict__ src) {
    size_t i = (size_t)blockIdx.x * blockDim.x + threadIdx.x;
    size_t n4 = (size_t)N1 * KD / 4;
    if (i >= n4) return;
    float4 v = ((const float4*)src)[i];
    v.x = to_tf32(v.x); v.y = to_tf32(v.y); v.z = to_tf32(v.z); v.w = to_tf32(v.w);
    ((float4*)g_We)[i] = v;
}
__global__ void round_Wp_k(const float* __restrict__ src) {
    size_t i = (size_t)blockIdx.x * blockDim.x + threadIdx.x;
    size_t n4 = (size_t)KD * KD / 4;
    if (i >= n4) return;
    float4 v = ((const float4*)src)[i];
    v.x = to_tf32(v.x); v.y = to_tf32(v.y); v.z = to_tf32(v.z); v.w = to_tf32(v.w);
    ((float4*)g_Wp)[i] = v;
}

// ---------------- rmsnorm ----------------
__global__ void __launch_bounds__(256) rmsnorm_k(const float* __restrict__ x) {
    int row = blockIdx.x;
    const float4* xr = (const float4*)(x + (size_t)row * DIMD);
    float4* outr = (float4*)(g_xn + (size_t)row * DIMD);
    int t = threadIdx.x;

    float4 a = xr[t];
    float4 b = xr[t + 256];
    float ss = a.x*a.x + a.y*a.y + a.z*a.z + a.w*a.w
             + b.x*b.x + b.y*b.y + b.z*b.z + b.w*b.w;
    #pragma unroll
    for (int off = 16; off > 0; off >>= 1)
        ss += __shfl_xor_sync(0xffffffffu, ss, off);

    __shared__ float red[8];
    __shared__ float sscale;
    int warp = t >> 5, lane = t & 31;
    if (lane == 0) red[warp] = ss;
    __syncthreads();
    if (t == 0) {
        float tot = 0.f;
        #pragma unroll
        for (int i = 0; i < 8; i++) tot += red[i];
        sscale = rsqrtf(tot * (1.0f / DIMD) + 1.1920928955078125e-07f);
    }
    __syncthreads();
    float sc = sscale;
    a.x = to_tf32(a.x * sc); a.y = to_tf32(a.y * sc); a.z = to_tf32(a.z * sc); a.w = to_tf32(a.w * sc);
    b.x = to_tf32(b.x * sc); b.y = to_tf32(b.y * sc); b.z = to_tf32(b.z * sc); b.w = to_tf32(b.w * sc);
    outr[t] = a;
    outr[t + 256] = b;
}

// ---------------- gate * causal dwconv * gate ----------------
__global__ void __launch_bounds__(256) gateconv_k(const float* __restrict__ cw,
                                                  const float* __restrict__ cb,
                                                  const int* __restrict__ dil_p) {
    int dil = *dil_p;
    size_t idx = (size_t)blockIdx.x * blockDim.x + threadIdx.x;
    if (idx >= (size_t)MTOT * DIMD) return;
    int d = (int)(idx % DIMD);
    int m = (int)(idx / DIMD);
    int s = m % SEQ;

    const float* hr = g_h + (size_t)m * N1;
    float w0 = cw[d * 3 + 0], w1 = cw[d * 3 + 1], w2 = cw[d * 3 + 2];

    float acc = cb[d];
    acc += w2 * (hr[d] * hr[2 * DIMD + d]);
    if (s >= dil) {
        const float* hp = hr - (size_t)dil * N1;
        acc += w1 * (hp[d] * hp[2 * DIMD + d]);
    }
    if (s >= 2 * dil) {
        const float* hp = hr - (size_t)(2 * dil) * N1;
        acc += w0 * (hp[d] * hp[2 * DIMD + d]);
    }
    float Cg = hr[DIMD + d];
    g_o[idx] = to_tf32(Cg * acc);
}

// ---------------- launch ----------------
extern "C" void kernel_launch(void* const* d_in, const int* in_sizes, int n_in,
                              void* d_out, int out_size) {
    const float* x   = (const float*)d_in[0];
    const float* We  = (const float*)d_in[1];
    const float* cw  = (const float*)d_in[2];
    const float* cb  = (const float*)d_in[3];
    const float* Wp  = (const float*)d_in[4];
    const float* cs  = (const float*)d_in[5];
    const int*   dil = (const int*)  d_in[6];
    float* out = (float*)d_out;

    float *p_xn, *p_h, *p_o, *p_We, *p_Wp;
    cudaGetSymbolAddress((void**)&p_xn, g_xn);
    cudaGetSymbolAddress((void**)&p_h,  g_h);
    cudaGetSymbolAddress((void**)&p_o,  g_o);
    cudaGetSymbolAddress((void**)&p_We, g_We);
    cudaGetSymbolAddress((void**)&p_Wp, g_Wp);

    cudaFuncSetAttribute(gemm_k<N1, false>, cudaFuncAttributeMaxDynamicSharedMemorySize, SMEM_SZ);
    cudaFuncSetAttribute(gemm_k<KD, true >, cudaFuncAttributeMaxDynamicSharedMemorySize, SMEM_SZ);

    {
        size_t n4 = (size_t)N1 * KD / 4;
        round_We_k<<<(unsigned)((n4 + 255) / 256), 256>>>(We);
        n4 = (size_t)KD * KD / 4;
        round_Wp_k<<<(unsigned)((n4 + 255) / 256), 256>>>(Wp);
    }

    rmsnorm_k<<<MTOT, 256>>>(x);

    // h = xn @ We^T   [16384 x 6144]
    gemm_k<N1, false><<<dim3(N1 / BN, MTOT / BM), NTHREADS, SMEM_SZ>>>(p_xn, p_We, p_h, nullptr, nullptr);

    {
        size_t n = (size_t)MTOT * DIMD;
        gateconv_k<<<(unsigned)((n + 255) / 256), 256>>>(cw, cb, dil);
    }

    // out = x + cs * (o @ Wp^T)   [16384 x 2048]
    gemm_k<KD, true><<<dim3(KD / BN, MTOT / BM), NTHREADS, SMEM_SZ>>>(p_o, p_Wp, out, x, cs);
}

// round 6
// speedup vs baseline: 1.1013x; 1.1013x over previous
#include <cuda_runtime.h>
#include <cstdint>
#include <cstddef>

// ---------------- problem constants ----------------
#define DIMD   2048
#define MTOT   16384            // 4*4096 tokens
#define N1     6144             // 3*DIMD
#define KD     2048
#define SEQ    4096

// ---------------- scratch ----------------
__device__ float g_xn[(size_t)MTOT * KD];
__device__ float g_h [(size_t)MTOT * N1];
__device__ float g_o [(size_t)MTOT * KD];
__device__ float g_We[(size_t)N1  * KD];
__device__ float g_Wp[(size_t)KD  * KD];

// ---------------- helpers ----------------
__device__ __forceinline__ float to_tf32(float x) {
    float r; asm("cvt.rna.tf32.f32 %0, %1;" : "=f"(r) : "f"(x)); return r;
}
__device__ __forceinline__ void cpasync16(void* smem, const void* gmem) {
    uint32_t s = (uint32_t)__cvta_generic_to_shared(smem);
    asm volatile("cp.async.cg.shared.global [%0], [%1], 16;" :: "r"(s), "l"(gmem));
}
#define CP_COMMIT() asm volatile("cp.async.commit_group;")
#define CP_WAIT1()  asm volatile("cp.async.wait_group 1;")

__device__ __forceinline__ void mma_tf32(float c[4], const uint32_t a[4], const uint32_t b[2]) {
    asm volatile(
        "mma.sync.aligned.m16n8k8.row.col.f32.tf32.tf32.f32 "
        "{%0,%1,%2,%3}, {%4,%5,%6,%7}, {%8,%9}, {%0,%1,%2,%3};"
        : "+f"(c[0]), "+f"(c[1]), "+f"(c[2]), "+f"(c[3])
        : "r"(a[0]), "r"(a[1]), "r"(a[2]), "r"(a[3]),
          "r"(b[0]), "r"(b[1]));
}

// ---------------- tf32 GEMM v6: C[M,N] = A[M,K] * B[N,K]^T ----------------
// CTA 128x256, 8 warps (2M x 4N), warp tile 64x64 (best LDS/MMA ratio = 1.0).
// BK=64 (8 ks-steps of k8 per smem tile) -> one __syncthreads per 8 MMA
// batches. 2-stage cp.async pipeline (209 KB smem) + register ping-pong.
constexpr int BM = 128, BN = 256, BK = 64, NSTG = 2;
constexpr int LDS_STRIDE = BK + 4;                   // 68 floats
constexpr int A_FLOATS = BM * LDS_STRIDE;            // 8704
constexpr int B_FLOATS = BN * LDS_STRIDE;            // 17408
constexpr int STG_FLOATS = A_FLOATS + B_FLOATS;      // 26112
constexpr int SMEM_SZ = NSTG * STG_FLOATS * 4;       // 208896 B

template<int N, bool FUSE>
__global__ void __launch_bounds__(256, 1) gemm_k(const float* __restrict__ A,
                                                 const float* __restrict__ B,
                                                 float* __restrict__ C,
                                                 const float* __restrict__ xres,
                                                 const float* __restrict__ cs) {
    constexpr int K = KD;
    constexpr int KT = K / BK;    // 32
    extern __shared__ float smem[];

    const int bm = blockIdx.y * BM;
    const int bn = blockIdx.x * BN;
    const int tid  = threadIdx.x;
    const int warp = tid >> 5, lane = tid & 31;
    const int wm = (warp & 1) * 64;
    const int wn = (warp >> 1) * 64;
    const int gid = lane >> 2, tig = lane & 3;

    float acc[4][8][4];
    #pragma unroll
    for (int mi = 0; mi < 4; mi++)
        #pragma unroll
        for (int ni = 0; ni < 8; ni++)
            #pragma unroll
            for (int r = 0; r < 4; r++) acc[mi][ni][r] = 0.f;

    const float* Abase = A + (size_t)bm * K;
    const float* Bbase = B + (size_t)bn * K;

    auto load_stage = [&](int kt) {
        float* sa = smem + (kt & 1) * STG_FLOATS;
        float* sb = sa + A_FLOATS;
        const float* Ag = Abase + kt * BK;
        const float* Bg = Bbase + kt * BK;
        // A: 128 rows x 16 chunks(16B) = 2048, 8 per thread
        #pragma unroll
        for (int i = 0; i < 8; i++) {
            int c = tid + i * 256;
            int row = c >> 4, ck = c & 15;
            cpasync16(sa + row * LDS_STRIDE + ck * 4, Ag + (size_t)row * K + ck * 4);
        }
        // B: 256 rows x 16 chunks = 4096, 16 per thread
        #pragma unroll
        for (int i = 0; i < 16; i++) {
            int c = tid + i * 256;
            int row = c >> 4, ck = c & 15;
            cpasync16(sb + row * LDS_STRIDE + ck * 4, Bg + (size_t)row * K + ck * 4);
        }
    };

    uint32_t fa[2][4][4];
    uint32_t fb[2][8][2];

    auto load_frags = [&](int buf, int stage, int ks) {
        const float* sa = smem + stage * STG_FLOATS;
        const float* sb = sa + A_FLOATS;
        const int k0 = ks * 8;
        #pragma unroll
        for (int mi = 0; mi < 4; mi++) {
            const float* p = sa + (wm + mi * 16 + gid) * LDS_STRIDE + k0;
            fa[buf][mi][0] = __float_as_uint(p[tig]);
            fa[buf][mi][1] = __float_as_uint(p[8 * LDS_STRIDE + tig]);
            fa[buf][mi][2] = __float_as_uint(p[tig + 4]);
            fa[buf][mi][3] = __float_as_uint(p[8 * LDS_STRIDE + tig + 4]);
        }
        #pragma unroll
        for (int ni = 0; ni < 8; ni++) {
            const float* p = sb + (wn + ni * 8 + gid) * LDS_STRIDE + k0;
            fb[buf][ni][0] = __float_as_uint(p[tig]);
            fb[buf][ni][1] = __float_as_uint(p[tig + 4]);
        }
    };

    auto mma_all = [&](int buf) {
        #pragma unroll
        for (int mi = 0; mi < 4; mi++)
            #pragma unroll
            for (int ni = 0; ni < 8; ni++)
                mma_tf32(acc[mi][ni], fa[buf][mi], fb[buf][ni]);
    };

    // prologue: both stages in flight
    load_stage(0); CP_COMMIT();
    load_stage(1); CP_COMMIT();
    CP_WAIT1();                 // stage 0 ready
    __syncthreads();
    load_frags(0, 0, 0);

    #pragma unroll 1
    for (int kt = 0; kt < KT; kt++) {
        const int stage = kt & 1;

        // ks 0..6: ping-pong within the tile
        #pragma unroll
        for (int ks = 0; ks < 7; ks++) {
            load_frags((ks ^ 1) & 1, stage, ks + 1);
            mma_all(ks & 1);
        }
        // ks 7: hand over to next tile
        if (kt + 1 < KT) {
            __syncthreads();               // stage kt fully consumed (ks7 frags in regs)
            load_stage(kt + 2 < KT ? kt + 2 : kt);   // refill freed buffer
            CP_COMMIT();
            CP_WAIT1();                    // stage kt+1 ready
            load_frags(0, stage ^ 1, 0);
        }
        mma_all(1);
    }

    // epilogue
    #pragma unroll
    for (int mi = 0; mi < 4; mi++) {
        #pragma unroll
        for (int ni = 0; ni < 8; ni++) {
            int r0 = bm + wm + mi * 16 + gid;
            int c0 = bn + wn + ni * 8 + tig * 2;
            #pragma unroll
            for (int h = 0; h < 2; h++) {
                int r = r0 + h * 8;
                size_t off = (size_t)r * N + c0;
                float v0 = acc[mi][ni][2 * h + 0];
                float v1 = acc[mi][ni][2 * h + 1];
                if (FUSE) {
                    v0 = xres[off]     + cs[c0]     * v0;
                    v1 = xres[off + 1] + cs[c0 + 1] * v1;
                }
                float2 st; st.x = v0; st.y = v1;
                *(float2*)(C + off) = st;
            }
        }
    }
}

// ---------------- prep: round weights to tf32 (RNA) ----------------
__global__ void round_We_k(const float* __restrict__ src) {
    size_t i = (size_t)blockIdx.x * blockDim.x + threadIdx.x;
    size_t n4 = (size_t)N1 * KD / 4;
    if (i >= n4) return;
    float4 v = ((const float4*)src)[i];
    v.x = to_tf32(v.x); v.y = to_tf32(v.y); v.z = to_tf32(v.z); v.w = to_tf32(v.w);
    ((float4*)g_We)[i] = v;
}
__global__ void round_Wp_k(const float* __restrict__ src) {
    size_t i = (size_t)blockIdx.x * blockDim.x + threadIdx.x;
    size_t n4 = (size_t)KD * KD / 4;
    if (i >= n4) return;
    float4 v = ((const float4*)src)[i];
    v.x = to_tf32(v.x); v.y = to_tf32(v.y); v.z = to_tf32(v.z); v.w = to_tf32(v.w);
    ((float4*)g_Wp)[i] = v;
}

// ---------------- rmsnorm ----------------
__global__ void __launch_bounds__(256) rmsnorm_k(const float* __restrict__ x) {
    int row = blockIdx.x;
    const float4* xr = (const float4*)(x + (size_t)row * DIMD);
    float4* outr = (float4*)(g_xn + (size_t)row * DIMD);
    int t = threadIdx.x;

    float4 a = xr[t];
    float4 b = xr[t + 256];
    float ss = a.x*a.x + a.y*a.y + a.z*a.z + a.w*a.w
             + b.x*b.x + b.y*b.y + b.z*b.z + b.w*b.w;
    #pragma unroll
    for (int off = 16; off > 0; off >>= 1)
        ss += __shfl_xor_sync(0xffffffffu, ss, off);

    __shared__ float red[8];
    __shared__ float sscale;
    int warp = t >> 5, lane = t & 31;
    if (lane == 0) red[warp] = ss;
    __syncthreads();
    if (t == 0) {
        float tot = 0.f;
        #pragma unroll
        for (int i = 0; i < 8; i++) tot += red[i];
        sscale = rsqrtf(tot * (1.0f / DIMD) + 1.1920928955078125e-07f);
    }
    __syncthreads();
    float sc = sscale;
    a.x = to_tf32(a.x * sc); a.y = to_tf32(a.y * sc); a.z = to_tf32(a.z * sc); a.w = to_tf32(a.w * sc);
    b.x = to_tf32(b.x * sc); b.y = to_tf32(b.y * sc); b.z = to_tf32(b.z * sc); b.w = to_tf32(b.w * sc);
    outr[t] = a;
    outr[t + 256] = b;
}

// ---------------- gate * causal dwconv * gate ----------------
__global__ void __launch_bounds__(256) gateconv_k(const float* __restrict__ cw,
                                                  const float* __restrict__ cb,
                                                  const int* __restrict__ dil_p) {
    int dil = *dil_p;
    size_t idx = (size_t)blockIdx.x * blockDim.x + threadIdx.x;
    if (idx >= (size_t)MTOT * DIMD) return;
    int d = (int)(idx % DIMD);
    int m = (int)(idx / DIMD);
    int s = m % SEQ;

    const float* hr = g_h + (size_t)m * N1;
    float w0 = cw[d * 3 + 0], w1 = cw[d * 3 + 1], w2 = cw[d * 3 + 2];

    float acc = cb[d];
    acc += w2 * (hr[d] * hr[2 * DIMD + d]);
    if (s >= dil) {
        const float* hp = hr - (size_t)dil * N1;
        acc += w1 * (hp[d] * hp[2 * DIMD + d]);
    }
    if (s >= 2 * dil) {
        const float* hp = hr - (size_t)(2 * dil) * N1;
        acc += w0 * (hp[d] * hp[2 * DIMD + d]);
    }
    float Cg = hr[DIMD + d];
    g_o[idx] = to_tf32(Cg * acc);
}

// ---------------- launch ----------------
extern "C" void kernel_launch(void* const* d_in, const int* in_sizes, int n_in,
                              void* d_out, int out_size) {
    const float* x   = (const float*)d_in[0];
    const float* We  = (const float*)d_in[1];
    const float* cw  = (const float*)d_in[2];
    const float* cb  = (const float*)d_in[3];
    const float* Wp  = (const float*)d_in[4];
    const float* cs  = (const float*)d_in[5];
    const int*   dil = (const int*)  d_in[6];
    float* out = (float*)d_out;

    float *p_xn, *p_h, *p_o, *p_We, *p_Wp;
    cudaGetSymbolAddress((void**)&p_xn, g_xn);
    cudaGetSymbolAddress((void**)&p_h,  g_h);
    cudaGetSymbolAddress((void**)&p_o,  g_o);
    cudaGetSymbolAddress((void**)&p_We, g_We);
    cudaGetSymbolAddress((void**)&p_Wp, g_Wp);

    cudaFuncSetAttribute(gemm_k<N1, false>, cudaFuncAttributeMaxDynamicSharedMemorySize, SMEM_SZ);
    cudaFuncSetAttribute(gemm_k<KD, true >, cudaFuncAttributeMaxDynamicSharedMemorySize, SMEM_SZ);

    {
        size_t n4 = (size_t)N1 * KD / 4;
        round_We_k<<<(unsigned)((n4 + 255) / 256), 256>>>(We);
        n4 = (size_t)KD * KD / 4;
        round_Wp_k<<<(unsigned)((n4 + 255) / 256), 256>>>(Wp);
    }

    rmsnorm_k<<<MTOT, 256>>>(x);

    // h = xn @ We^T   [16384 x 6144]
    gemm_k<N1, false><<<dim3(N1 / BN, MTOT / BM), 256, SMEM_SZ>>>(p_xn, p_We, p_h, nullptr, nullptr);

    {
        size_t n = (size_t)MTOT * DIMD;
        gateconv_k<<<(unsigned)((n + 255) / 256), 256>>>(cw, cb, dil);
    }

    // out = x + cs * (o @ Wp^T)   [16384 x 2048]
    gemm_k<KD, true><<<dim3(KD / BN, MTOT / BM), 256, SMEM_SZ>>>(p_o, p_Wp, out, x, cs);
}